// round 1
// baseline (speedup 1.0000x reference)
#include <cuda_runtime.h>
#include <math.h>

#define Hs   64
#define SEQ  2048
#define Bt   256
#define IN   32

__device__ __forceinline__ float sigf(float v) { return 1.0f / (1.0f + expf(-v)); }

// Dynamic smem layout (floats):
//  [0, 16384)           Whh1 as float4 [k4=16][gj=256]  (64 KB)
//  [16384, 16640)       combined bias layer0 (256)
//  [16640, 16896)       combined bias layer1 (256)
//  [16896, 16960)       Wh (64)
//  [16960, 17472)       gate buffer [row=2][256]
//  [17472, 17600)       h layer0 [row=2][64]
//  [17600, 17728)       h layer1 [row=2][64]
//  [17728, 17856)       x double buffer [parity=2][row=2][32]
//  [17856, 17864)       prob partials (4) + pad
#define SMEM_FLOATS 17864

__global__ void __launch_bounds__(256, 1)
lstm2_fused(const float* __restrict__ x,
            const float* __restrict__ h0g,
            const float* __restrict__ c0g,
            const float* __restrict__ Wih0,
            const float* __restrict__ Whh0,
            const float* __restrict__ bih0,
            const float* __restrict__ bhh0,
            const float* __restrict__ Wih1,
            const float* __restrict__ Whh1,
            const float* __restrict__ bih1,
            const float* __restrict__ bhh1,
            const float* __restrict__ Wh,
            const float* __restrict__ bhp,
            float* __restrict__ out)
{
    extern __shared__ float sm[];
    float4* sW1h = (float4*)sm;          // [k4][gj]
    float*  sB0  = sm + 16384;
    float*  sB1  = sB0 + 256;
    float*  sWh  = sB1 + 256;
    float*  sG   = sWh + 64;             // [2][256]
    float*  sH0  = sG + 512;             // [2][64]
    float*  sH1  = sH0 + 128;            // [2][64]
    float*  sX   = sH1 + 128;            // [2][2][32]
    float*  sPr  = sX + 128;             // [4]

    const int tid = threadIdx.x;         // == gj (gate row 0..255)
    const int r0  = blockIdx.x * 2;      // global batch rows r0, r0+1

    // ---- per-thread register weights: rows of Wih0, Whh0, Wih1 for gate `tid`
    float wx0[IN];
    float wh0[Hs];
    float wx1[Hs];
#pragma unroll
    for (int k = 0; k < IN; k++) wx0[k] = Wih0[tid * IN + k];
#pragma unroll
    for (int k = 0; k < Hs; k++) wh0[k] = Whh0[tid * Hs + k];
#pragma unroll
    for (int k = 0; k < Hs; k++) wx1[k] = Wih1[tid * Hs + k];

    // ---- smem init
    for (int idx = tid; idx < 16 * 256; idx += 256) {
        int gj = idx & 255, k4 = idx >> 8;
        sW1h[idx] = *(const float4*)(Whh1 + gj * Hs + k4 * 4);
    }
    sB0[tid] = bih0[tid] + bhh0[tid];
    sB1[tid] = bih1[tid] + bhh1[tid];
    if (tid < 64) sWh[tid] = Wh[tid];

    float c0r = 0.0f, c1r = 0.0f;
    if (tid < 128) {
        int r = tid >> 6, j = tid & 63;
        sH0[r * 64 + j] = h0g[(size_t)(r0 + r) * Hs + j];
        sH1[r * 64 + j] = h0g[(size_t)Bt * Hs + (size_t)(r0 + r) * Hs + j];
        c0r = c0g[(size_t)(r0 + r) * Hs + j];
        c1r = c0g[(size_t)Bt * Hs + (size_t)(r0 + r) * Hs + j];
    }
    if (tid < 16) {
        int row = tid >> 3, q = tid & 7;
        float4 v = *(const float4*)(x + (size_t)(r0 + row) * SEQ * IN + q * 4);
        ((float4*)sX)[row * 8 + q] = v;
    }
    __syncthreads();

    const float bh0 = bhp[0];

    for (int t = 0; t < SEQ; t++) {
        // prefetch x for t+1 into registers (latency hidden under compute)
        float4 xf = make_float4(0.f, 0.f, 0.f, 0.f);
        if (tid < 16 && t + 1 < SEQ) {
            int row = tid >> 3, q = tid & 7;
            xf = *(const float4*)(x + (size_t)(r0 + row) * SEQ * IN
                                    + (size_t)(t + 1) * IN + q * 4);
        }

        // ================= layer 0 gates =================
        const float* xr0 = sX + (t & 1) * 64;
        const float* xr1 = xr0 + 32;
        float a0 = sB0[tid], a1 = a0;
#pragma unroll
        for (int k4 = 0; k4 < IN / 4; k4++) {
            float4 v0 = *(const float4*)(xr0 + k4 * 4);
            float4 v1 = *(const float4*)(xr1 + k4 * 4);
            a0 = fmaf(wx0[k4*4+0], v0.x, a0); a1 = fmaf(wx0[k4*4+0], v1.x, a1);
            a0 = fmaf(wx0[k4*4+1], v0.y, a0); a1 = fmaf(wx0[k4*4+1], v1.y, a1);
            a0 = fmaf(wx0[k4*4+2], v0.z, a0); a1 = fmaf(wx0[k4*4+2], v1.z, a1);
            a0 = fmaf(wx0[k4*4+3], v0.w, a0); a1 = fmaf(wx0[k4*4+3], v1.w, a1);
        }
#pragma unroll
        for (int k4 = 0; k4 < Hs / 4; k4++) {
            float4 v0 = *(const float4*)(sH0 + k4 * 4);
            float4 v1 = *(const float4*)(sH0 + 64 + k4 * 4);
            a0 = fmaf(wh0[k4*4+0], v0.x, a0); a1 = fmaf(wh0[k4*4+0], v1.x, a1);
            a0 = fmaf(wh0[k4*4+1], v0.y, a0); a1 = fmaf(wh0[k4*4+1], v1.y, a1);
            a0 = fmaf(wh0[k4*4+2], v0.z, a0); a1 = fmaf(wh0[k4*4+2], v1.z, a1);
            a0 = fmaf(wh0[k4*4+3], v0.w, a0); a1 = fmaf(wh0[k4*4+3], v1.w, a1);
        }
        sG[tid] = a0; sG[256 + tid] = a1;
        __syncthreads();

        // ================= layer 0 cell update =================
        if (tid < 128) {
            int r = tid >> 6, j = tid & 63;
            float ig = sigf(sG[r * 256 + j]);
            float fg = sigf(sG[r * 256 + 64 + j]);
            float gg = tanhf(sG[r * 256 + 128 + j]);
            float og = sigf(sG[r * 256 + 192 + j]);
            c0r = fg * c0r + ig * gg;
            sH0[r * 64 + j] = og * tanhf(c0r);
        }
        __syncthreads();

        // ================= layer 1 gates =================
        a0 = sB1[tid]; a1 = a0;
#pragma unroll
        for (int k4 = 0; k4 < Hs / 4; k4++) {
            float4 v0 = *(const float4*)(sH0 + k4 * 4);
            float4 v1 = *(const float4*)(sH0 + 64 + k4 * 4);
            a0 = fmaf(wx1[k4*4+0], v0.x, a0); a1 = fmaf(wx1[k4*4+0], v1.x, a1);
            a0 = fmaf(wx1[k4*4+1], v0.y, a0); a1 = fmaf(wx1[k4*4+1], v1.y, a1);
            a0 = fmaf(wx1[k4*4+2], v0.z, a0); a1 = fmaf(wx1[k4*4+2], v1.z, a1);
            a0 = fmaf(wx1[k4*4+3], v0.w, a0); a1 = fmaf(wx1[k4*4+3], v1.w, a1);
        }
#pragma unroll
        for (int k4 = 0; k4 < Hs / 4; k4++) {
            float4 w  = sW1h[k4 * 256 + tid];
            float4 v0 = *(const float4*)(sH1 + k4 * 4);
            float4 v1 = *(const float4*)(sH1 + 64 + k4 * 4);
            a0 = fmaf(w.x, v0.x, a0); a1 = fmaf(w.x, v1.x, a1);
            a0 = fmaf(w.y, v0.y, a0); a1 = fmaf(w.y, v1.y, a1);
            a0 = fmaf(w.z, v0.z, a0); a1 = fmaf(w.z, v1.z, a1);
            a0 = fmaf(w.w, v0.w, a0); a1 = fmaf(w.w, v1.w, a1);
        }
        sG[tid] = a0; sG[256 + tid] = a1;
        __syncthreads();

        // ================= layer 1 cell update + head =================
        if (tid < 128) {
            int r = tid >> 6, j = tid & 63;
            float ig = sigf(sG[r * 256 + j]);
            float fg = sigf(sG[r * 256 + 64 + j]);
            float gg = tanhf(sG[r * 256 + 128 + j]);
            float og = sigf(sG[r * 256 + 192 + j]);
            c1r = fg * c1r + ig * gg;
            float hn = og * tanhf(c1r);
            sH1[r * 64 + j] = hn;
            float p = hn * sWh[j];
#pragma unroll
            for (int off = 16; off; off >>= 1)
                p += __shfl_down_sync(0xffffffffu, p, off);
            if ((tid & 31) == 0) sPr[tid >> 5] = p;   // warp 0..3 partials
        }
        // stage prefetched x(t+1) into the alternate buffer
        if (tid < 16 && t + 1 < SEQ) {
            int row = tid >> 3, q = tid & 7;
            ((float4*)sX)[((t + 1) & 1) * 16 + row * 8 + q] = xf;
        }
        __syncthreads();

        if (tid < 2) {
            float v = sPr[tid * 2] + sPr[tid * 2 + 1] + bh0;
            out[(size_t)(r0 + tid) * SEQ + t] = 1.0f / (1.0f + expf(-v));
        }
    }

    // ---- final h, c
    if (tid < 128) {
        int r = tid >> 6, j = tid & 63;
        const size_t hb = (size_t)Bt * SEQ;          // 524288
        const size_t cb = hb + 2 * (size_t)Bt * Hs;  // 557056
        out[hb + (size_t)(r0 + r) * Hs + j]            = sH0[r * 64 + j];
        out[hb + Bt * Hs + (size_t)(r0 + r) * Hs + j]  = sH1[r * 64 + j];
        out[cb + (size_t)(r0 + r) * Hs + j]            = c0r;
        out[cb + Bt * Hs + (size_t)(r0 + r) * Hs + j]  = c1r;
    }
}

extern "C" void kernel_launch(void* const* d_in, const int* in_sizes, int n_in,
                              void* d_out, int out_size)
{
    const float* x    = (const float*)d_in[0];
    const float* h0   = (const float*)d_in[1];
    const float* c0   = (const float*)d_in[2];
    const float* Wih0 = (const float*)d_in[3];
    const float* Whh0 = (const float*)d_in[4];
    const float* bih0 = (const float*)d_in[5];
    const float* bhh0 = (const float*)d_in[6];
    const float* Wih1 = (const float*)d_in[7];
    const float* Whh1 = (const float*)d_in[8];
    const float* bih1 = (const float*)d_in[9];
    const float* bhh1 = (const float*)d_in[10];
    const float* Wh   = (const float*)d_in[11];
    const float* bh   = (const float*)d_in[12];
    float* out = (float*)d_out;

    const int smem_bytes = SMEM_FLOATS * (int)sizeof(float);
    cudaFuncSetAttribute(lstm2_fused,
                         cudaFuncAttributeMaxDynamicSharedMemorySize, smem_bytes);
    lstm2_fused<<<Bt / 2, 256, smem_bytes>>>(
        x, h0, c0, Wih0, Whh0, bih0, bhh0,
        Wih1, Whh1, bih1, bhh1, Wh, bh, out);
}

// round 2
// speedup vs baseline: 1.1917x; 1.1917x over previous
#include <cuda_runtime.h>
#include <math.h>

#define Hs   64
#define SEQ  2048
#define Bt   256
#define IN   32

typedef unsigned long long u64;

__device__ __forceinline__ u64 fma2(u64 a, u64 b, u64 c) {
    u64 d;
    asm("fma.rn.f32x2 %0, %1, %2, %3;" : "=l"(d) : "l"(a), "l"(b), "l"(c));
    return d;
}
__device__ __forceinline__ u64 pk(float a, float b) {
    u64 r;
    asm("mov.b64 %0, {%1, %2};" : "=l"(r) : "f"(a), "f"(b));
    return r;
}
__device__ __forceinline__ float hsum(u64 v) {
    float a, b;
    asm("mov.b64 {%0, %1}, %2;" : "=f"(a), "=f"(b) : "l"(v));
    return a + b;
}
__device__ __forceinline__ float ex2a(float x) {
    float y; asm("ex2.approx.f32 %0, %1;" : "=f"(y) : "f"(x)); return y;
}
__device__ __forceinline__ float rcpa(float x) {
    float y; asm("rcp.approx.f32 %0, %1;" : "=f"(y) : "f"(x)); return y;
}
// sigmoid via ex2/rcp approx: rel err ~1e-6
__device__ __forceinline__ float sigf(float x) {
    return rcpa(1.0f + ex2a(-1.4426950408889634f * x));
}
// tanh(x) = 2*sigmoid(2x) - 1, same precision class
__device__ __forceinline__ float tanhfa(float x) {
    return fmaf(2.0f, sigf(2.0f * x), -1.0f);
}

// Dynamic smem layout (floats):
//  [0, 16384)       Whh1 as float4 [k4=16][gj=256]  (64 KB)
//  [16384, 16448)   Wh (64)
//  [16448, 16960)   gate buffer (ACTIVATED) [row=2][256]
//  [16960, 17088)   h layer0 [row=2][64]
//  [17088, 17216)   h layer1 [row=2][64]
//  [17216, 17344)   x double buffer [parity=2][row=2][32]
//  [17344, 17348)   prob partials (4)
#define SMEM_FLOATS 17352

__global__ void __launch_bounds__(256, 1)
lstm2_fused(const float* __restrict__ x,
            const float* __restrict__ h0g,
            const float* __restrict__ c0g,
            const float* __restrict__ Wih0,
            const float* __restrict__ Whh0,
            const float* __restrict__ bih0,
            const float* __restrict__ bhh0,
            const float* __restrict__ Wih1,
            const float* __restrict__ Whh1,
            const float* __restrict__ bih1,
            const float* __restrict__ bhh1,
            const float* __restrict__ Wh,
            const float* __restrict__ bhp,
            float* __restrict__ out)
{
    extern __shared__ float sm[];
    float* sW1h = sm;                    // float4 [k4][gj]
    float* sWh  = sm + 16384;
    float* sG   = sWh + 64;              // [2][256]
    float* sH0  = sG + 512;              // [2][64]
    float* sH1  = sH0 + 128;             // [2][64]
    float* sX   = sH1 + 128;             // [2][2][32]
    float* sPr  = sX + 128;              // [4]

    const int tid = threadIdx.x;         // gate row 0..255
    const int r0  = blockIdx.x * 2;

    // ---- per-thread register weights as f32x2 pairs (lanes = k even/odd)
    u64 wx0[IN / 2];    // 16
    u64 wh0[Hs / 2];    // 32
    u64 wx1[Hs / 2];    // 32
    {
        const u64* p0 = (const u64*)(Wih0 + tid * IN);
        const u64* p1 = (const u64*)(Whh0 + tid * Hs);
        const u64* p2 = (const u64*)(Wih1 + tid * Hs);
#pragma unroll
        for (int k = 0; k < IN / 2; k++) wx0[k] = p0[k];
#pragma unroll
        for (int k = 0; k < Hs / 2; k++) wh0[k] = p1[k];
#pragma unroll
        for (int k = 0; k < Hs / 2; k++) wx1[k] = p2[k];
    }
    // biases packed into accumulator-init registers ({bias, 0})
    const u64 b0p = pk(bih0[tid] + bhh0[tid], 0.0f);
    const u64 b1p = pk(bih1[tid] + bhh1[tid], 0.0f);
    const int gsel = tid >> 6;           // 0:i 1:f 2:g 3:o (uniform per warp-pair)

    // ---- smem init
    for (int idx = tid; idx < 16 * 256; idx += 256) {
        int gj = idx & 255, k4 = idx >> 8;
        ((float4*)sW1h)[idx] = *(const float4*)(Whh1 + gj * Hs + k4 * 4);
    }
    if (tid < 64) sWh[tid] = Wh[tid];

    float c0r = 0.0f, c1r = 0.0f;
    if (tid < 128) {
        int r = tid >> 6, j = tid & 63;
        sH0[r * 64 + j] = h0g[(size_t)(r0 + r) * Hs + j];
        sH1[r * 64 + j] = h0g[(size_t)Bt * Hs + (size_t)(r0 + r) * Hs + j];
        c0r = c0g[(size_t)(r0 + r) * Hs + j];
        c1r = c0g[(size_t)Bt * Hs + (size_t)(r0 + r) * Hs + j];
    }
    if (tid < 16) {
        int row = tid >> 3, q = tid & 7;
        ((float4*)sX)[row * 8 + q] =
            *(const float4*)(x + (size_t)(r0 + row) * SEQ * IN + q * 4);
    }
    __syncthreads();

    const float bh0 = bhp[0];

    for (int t = 0; t < SEQ; t++) {
        // prefetch x(t+1)
        float4 xf = make_float4(0.f, 0.f, 0.f, 0.f);
        if (tid < 16 && t + 1 < SEQ) {
            int row = tid >> 3, q = tid & 7;
            xf = *(const float4*)(x + (size_t)(r0 + row) * SEQ * IN
                                    + (size_t)(t + 1) * IN + q * 4);
        }

        // ================= layer 0 gates (f32x2) =================
        const ulonglong2* xr0 = (const ulonglong2*)(sX + (t & 1) * 64);
        const ulonglong2* xr1 = (const ulonglong2*)(sX + (t & 1) * 64 + 32);
        const ulonglong2* h0a = (const ulonglong2*)sH0;
        const ulonglong2* h0b = (const ulonglong2*)(sH0 + 64);
        u64 a0 = b0p, a1 = b0p;
#pragma unroll
        for (int k = 0; k < 8; k++) {          // x: 32 floats = 8 x 16B per row
            ulonglong2 v0 = xr0[k];
            ulonglong2 v1 = xr1[k];
            a0 = fma2(wx0[2*k],   v0.x, a0);
            a0 = fma2(wx0[2*k+1], v0.y, a0);
            a1 = fma2(wx0[2*k],   v1.x, a1);
            a1 = fma2(wx0[2*k+1], v1.y, a1);
        }
#pragma unroll
        for (int k = 0; k < 16; k++) {         // h: 64 floats = 16 x 16B per row
            ulonglong2 v0 = h0a[k];
            ulonglong2 v1 = h0b[k];
            a0 = fma2(wh0[2*k],   v0.x, a0);
            a0 = fma2(wh0[2*k+1], v0.y, a0);
            a1 = fma2(wh0[2*k],   v1.x, a1);
            a1 = fma2(wh0[2*k+1], v1.y, a1);
        }
        {
            float g0 = hsum(a0), g1 = hsum(a1);
            float act0 = (gsel == 2) ? tanhfa(g0) : sigf(g0);
            float act1 = (gsel == 2) ? tanhfa(g1) : sigf(g1);
            sG[tid] = act0; sG[256 + tid] = act1;
        }
        __syncthreads();

        // ================= layer 0 cell update =================
        if (tid < 128) {
            int r = tid >> 6, j = tid & 63;
            float ig = sG[r * 256 + j];
            float fg = sG[r * 256 + 64 + j];
            float gg = sG[r * 256 + 128 + j];
            float og = sG[r * 256 + 192 + j];
            c0r = fg * c0r + ig * gg;
            sH0[r * 64 + j] = og * tanhfa(c0r);
        }
        __syncthreads();

        // ================= layer 1 gates (f32x2) =================
        a0 = b1p; a1 = b1p;
#pragma unroll
        for (int k = 0; k < 16; k++) {         // input = updated h_l0
            ulonglong2 v0 = h0a[k];
            ulonglong2 v1 = h0b[k];
            a0 = fma2(wx1[2*k],   v0.x, a0);
            a0 = fma2(wx1[2*k+1], v0.y, a0);
            a1 = fma2(wx1[2*k],   v1.x, a1);
            a1 = fma2(wx1[2*k+1], v1.y, a1);
        }
        {
            const ulonglong2* wp  = (const ulonglong2*)sW1h;
            const ulonglong2* h1a = (const ulonglong2*)sH1;
            const ulonglong2* h1b = (const ulonglong2*)(sH1 + 64);
#pragma unroll
            for (int k4 = 0; k4 < 16; k4++) {  // recurrent Whh1 from smem
                ulonglong2 w  = wp[k4 * 256 + tid];
                ulonglong2 v0 = h1a[k4];
                ulonglong2 v1 = h1b[k4];
                a0 = fma2(w.x, v0.x, a0);
                a0 = fma2(w.y, v0.y, a0);
                a1 = fma2(w.x, v1.x, a1);
                a1 = fma2(w.y, v1.y, a1);
            }
        }
        {
            float g0 = hsum(a0), g1 = hsum(a1);
            float act0 = (gsel == 2) ? tanhfa(g0) : sigf(g0);
            float act1 = (gsel == 2) ? tanhfa(g1) : sigf(g1);
            sG[tid] = act0; sG[256 + tid] = act1;
        }
        __syncthreads();

        // ================= layer 1 cell update + head =================
        if (tid < 128) {
            int r = tid >> 6, j = tid & 63;
            float ig = sG[r * 256 + j];
            float fg = sG[r * 256 + 64 + j];
            float gg = sG[r * 256 + 128 + j];
            float og = sG[r * 256 + 192 + j];
            c1r = fg * c1r + ig * gg;
            float hn = og * tanhfa(c1r);
            sH1[r * 64 + j] = hn;
            float p = hn * sWh[j];
#pragma unroll
            for (int off = 16; off; off >>= 1)
                p += __shfl_down_sync(0xffffffffu, p, off);
            if ((tid & 31) == 0) sPr[tid >> 5] = p;
        }
        if (tid < 16 && t + 1 < SEQ) {
            int row = tid >> 3, q = tid & 7;
            ((float4*)sX)[((t + 1) & 1) * 16 + row * 8 + q] = xf;
        }
        __syncthreads();

        if (tid < 2) {
            float v = sPr[tid * 2] + sPr[tid * 2 + 1] + bh0;
            out[(size_t)(r0 + tid) * SEQ + t] = sigf(v);
        }
    }

    // ---- final h, c
    if (tid < 128) {
        int r = tid >> 6, j = tid & 63;
        const size_t hb = (size_t)Bt * SEQ;
        const size_t cb = hb + 2 * (size_t)Bt * Hs;
        out[hb + (size_t)(r0 + r) * Hs + j]            = sH0[r * 64 + j];
        out[hb + Bt * Hs + (size_t)(r0 + r) * Hs + j]  = sH1[r * 64 + j];
        out[cb + (size_t)(r0 + r) * Hs + j]            = c0r;
        out[cb + Bt * Hs + (size_t)(r0 + r) * Hs + j]  = c1r;
    }
}

extern "C" void kernel_launch(void* const* d_in, const int* in_sizes, int n_in,
                              void* d_out, int out_size)
{
    const float* x    = (const float*)d_in[0];
    const float* h0   = (const float*)d_in[1];
    const float* c0   = (const float*)d_in[2];
    const float* Wih0 = (const float*)d_in[3];
    const float* Whh0 = (const float*)d_in[4];
    const float* bih0 = (const float*)d_in[5];
    const float* bhh0 = (const float*)d_in[6];
    const float* Wih1 = (const float*)d_in[7];
    const float* Whh1 = (const float*)d_in[8];
    const float* bih1 = (const float*)d_in[9];
    const float* bhh1 = (const float*)d_in[10];
    const float* Wh   = (const float*)d_in[11];
    const float* bh   = (const float*)d_in[12];
    float* out = (float*)d_out;

    const int smem_bytes = SMEM_FLOATS * (int)sizeof(float);
    cudaFuncSetAttribute(lstm2_fused,
                         cudaFuncAttributeMaxDynamicSharedMemorySize, smem_bytes);
    lstm2_fused<<<Bt / 2, 256, smem_bytes>>>(
        x, h0, c0, Wih0, Whh0, bih0, bhh0,
        Wih1, Whh1, bih1, bhh1, Wh, bh, out);
}